// round 9
// baseline (speedup 1.0000x reference)
#include <cuda_runtime.h>
#include <cuda_bf16.h>
#include <cstdint>

// Problem constants
#define BATCH 512
#define DD 512
#define NITER 7
#define SPLITK 2
#define KPER (DD / SPLITK)      // 256 per CTA
#define BK 64                   // k-chunk staged in smem
#define APITCH 72               // padded smem pitch (bank-conflict-free ldmatrix)
#define NCTA 128                // persistent grid (1 CTA/SM, all co-resident)

// ---------------------------------------------------------------------------
// Scratch (device globals — no allocation allowed)
// ---------------------------------------------------------------------------
__device__ float g_r[BATCH * DD];
__device__ float g_p[BATCH * DD];
__device__ float g_y[BATCH * DD];
__device__ float g_qp[SPLITK][BATCH * DD];
__device__ __nv_bfloat16 g_p_hi[BATCH * DD];
__device__ __nv_bfloat16 g_p_lo[BATCH * DD];
__device__ __nv_bfloat16 g_c_hi[DD * DD];
__device__ __nv_bfloat16 g_c_lo[DD * DD];
__device__ float g_shift[BATCH];
__device__ float g_oscale[BATCH];
__device__ float g_rr[BATCH];
__device__ unsigned g_bar_count;
__device__ volatile unsigned g_bar_gen;

// ---------------------------------------------------------------------------
// PTX helpers (sm_80-era instructions only — safe for plain sm_103 ptxas)
// ---------------------------------------------------------------------------
__device__ __forceinline__ uint32_t smem_u32(const void* p) {
    uint32_t a;
    asm("{ .reg .u64 t; cvta.to.shared.u64 t, %1; cvt.u32.u64 %0, t; }"
        : "=r"(a) : "l"(p));
    return a;
}

__device__ __forceinline__ void ldsm4(uint32_t* r, uint32_t addr) {
    asm volatile("ldmatrix.sync.aligned.m8n8.x4.shared.b16 {%0,%1,%2,%3}, [%4];"
                 : "=r"(r[0]), "=r"(r[1]), "=r"(r[2]), "=r"(r[3]) : "r"(addr));
}

__device__ __forceinline__ void mma_bf16(float* d, const uint32_t* a,
                                         uint32_t b0, uint32_t b1) {
    asm volatile(
        "mma.sync.aligned.m16n8k16.row.col.f32.bf16.bf16.f32 "
        "{%0,%1,%2,%3}, {%4,%5,%6,%7}, {%8,%9}, {%0,%1,%2,%3};"
        : "+f"(d[0]), "+f"(d[1]), "+f"(d[2]), "+f"(d[3])
        : "r"(a[0]), "r"(a[1]), "r"(a[2]), "r"(a[3]), "r"(b0), "r"(b1));
}

__device__ __forceinline__ float warp_sum(float v) {
#pragma unroll
    for (int m = 16; m > 0; m >>= 1)
        v += __shfl_xor_sync(0xFFFFFFFFu, v, m);
    return v;
}

// Self-resetting generation-counter grid barrier. Safe: all NCTA CTAs
// co-resident (1 per SM). Deterministic.
__device__ __forceinline__ void grid_barrier() {
    __syncthreads();
    __threadfence();
    if (threadIdx.x == 0) {
        unsigned gen = g_bar_gen;
        if (atomicAdd(&g_bar_count, 1u) == NCTA - 1) {
            atomicExch(&g_bar_count, 0u);
            __threadfence();
            g_bar_gen = gen + 1;
        } else {
            while (g_bar_gen == gen) { }
        }
    }
    __syncthreads();
    __threadfence();
}

// ---------------------------------------------------------------------------
// Init: per-batch scalars, rhs = exp(0.5 B) x - mu ; r = p = rhs ; y = 0 ;
// rr = ||rhs||^2 ; p hi/lo bf16 split
// ---------------------------------------------------------------------------
__global__ __launch_bounds__(256) void init_kernel(const float* __restrict__ x,
                                                   const float* __restrict__ t,
                                                   const float* __restrict__ mu) {
    int b = blockIdx.x;
    int tid = threadIdx.x;
    float tv = t[b];
    float B = 9.95f * tv * tv + 0.1f * tv;
    float eh = expf(0.5f * B);
    float shift = expm1f(B);
    float rescale = sqrtf(-expm1f(-B));
    if (tid == 0) {
        g_shift[b] = shift;
        g_oscale[b] = -(eh * rescale);
    }
    float acc = 0.0f;
    __shared__ float sred[256];
#pragma unroll
    for (int k = 0; k < 2; k++) {
        int i = b * DD + tid + k * 256;
        float v = eh * x[i] - mu[tid + k * 256];
        g_r[i] = v;
        g_p[i] = v;
        g_y[i] = 0.0f;
        __nv_bfloat16 h = __float2bfloat16(v);
        g_p_hi[i] = h;
        g_p_lo[i] = __float2bfloat16(v - __bfloat162float(h));
        acc += v * v;
    }
    sred[tid] = acc;
    __syncthreads();
    for (int s = 128; s > 0; s >>= 1) {
        if (tid < s) sred[tid] += sred[tid + s];
        __syncthreads();
    }
    if (tid == 0) g_rr[b] = sred[0];
}

// ---------------------------------------------------------------------------
// Prep C: bf16 hi/lo split of posterior_cov (symmetric: row n == col n)
// ---------------------------------------------------------------------------
__global__ __launch_bounds__(256) void prep_c_kernel(const float* __restrict__ cov) {
    int i = blockIdx.x;
    int tid = threadIdx.x;
#pragma unroll
    for (int k = 0; k < 2; k++) {
        int idx = i * DD + tid + k * 256;
        float v = cov[idx];
        __nv_bfloat16 h = __float2bfloat16(v);
        g_c_hi[idx] = h;
        g_c_lo[idx] = __float2bfloat16(v - __bfloat162float(h));
    }
}

// ---------------------------------------------------------------------------
// Persistent fused CG: GEMM phase + grid barrier + CG-update phase, NITER x.
// 128 CTAs x 128 threads. GEMM core identical to validated R6/R7 kernel.
// ---------------------------------------------------------------------------
__global__ __launch_bounds__(128) void cg_persistent_kernel(float* __restrict__ out) {
    __shared__ __nv_bfloat16 sAhi[64][APITCH];
    __shared__ __nv_bfloat16 sAlo[64][APITCH];
    __shared__ __nv_bfloat16 sBhi[64][APITCH];
    __shared__ __nv_bfloat16 sBlo[64][APITCH];

    const int cta = blockIdx.x;
    const int tid = threadIdx.x;
    const int lid = tid & 31;
    const int wid = tid >> 5;

    // GEMM tile assignment
    const int bm = ((cta >> 3) & 7) * 64;
    const int bn = (cta & 7) * 64;
    const int kbase = (cta >> 6) * KPER;
    const int wm = (wid & 1) * 32;
    const int wn = (wid >> 1) * 32;
    const int lrow = lid & 15;
    const int lcol8 = (lid >> 4) * 8;
    float* qp = g_qp[cta >> 6];

    // CG row assignment: warp-per-row
    const int crow = cta * 4 + wid;
    const int cbase = crow * DD + lid * 4;

    for (int it = 0; it < NITER; it++) {
        // ============ GEMM phase ============
        float acc[2][4][4];
#pragma unroll
        for (int i = 0; i < 2; i++)
#pragma unroll
            for (int j = 0; j < 4; j++)
#pragma unroll
                for (int v = 0; v < 4; v++) acc[i][j][v] = 0.0f;

        for (int kc = kbase; kc < kbase + KPER; kc += BK) {
            __syncthreads();
#pragma unroll
            for (int i = 0; i < 4; i++) {
                int slot = tid + 128 * i;
                int row = slot >> 3;
                int c8 = (slot & 7) * 8;
                *(uint4*)&sAhi[row][c8] = *(const uint4*)&g_p_hi[(bm + row) * DD + kc + c8];
                *(uint4*)&sAlo[row][c8] = *(const uint4*)&g_p_lo[(bm + row) * DD + kc + c8];
                *(uint4*)&sBhi[row][c8] = *(const uint4*)&g_c_hi[(bn + row) * DD + kc + c8];
                *(uint4*)&sBlo[row][c8] = *(const uint4*)&g_c_lo[(bn + row) * DD + kc + c8];
            }
            __syncthreads();

#pragma unroll
            for (int ks = 0; ks < BK / 16; ks++) {
                int kk = ks * 16 + lcol8;
                uint32_t ahi[2][4], alo[2][4], bhi[2][4], blo[2][4];
#pragma unroll
                for (int mi = 0; mi < 2; mi++) {
                    ldsm4(ahi[mi], smem_u32(&sAhi[wm + mi * 16 + lrow][kk]));
                    ldsm4(alo[mi], smem_u32(&sAlo[wm + mi * 16 + lrow][kk]));
                }
#pragma unroll
                for (int nh = 0; nh < 2; nh++) {
                    ldsm4(bhi[nh], smem_u32(&sBhi[wn + nh * 16 + lrow][kk]));
                    ldsm4(blo[nh], smem_u32(&sBlo[wn + nh * 16 + lrow][kk]));
                }
#pragma unroll
                for (int mi = 0; mi < 2; mi++)
#pragma unroll
                    for (int ni = 0; ni < 4; ni++) {
                        int nh = ni >> 1, sb = ni & 1;
                        mma_bf16(acc[mi][ni], ahi[mi], bhi[nh][sb], bhi[nh][sb + 2]);
                        mma_bf16(acc[mi][ni], ahi[mi], blo[nh][sb], blo[nh][sb + 2]);
                        mma_bf16(acc[mi][ni], alo[mi], bhi[nh][sb], bhi[nh][sb + 2]);
                    }
            }
        }

        const int g = lid >> 2, tq = lid & 3;
#pragma unroll
        for (int mi = 0; mi < 2; mi++)
#pragma unroll
            for (int ni = 0; ni < 4; ni++) {
                int row = bm + wm + mi * 16 + g;
                int col = bn + wn + ni * 8 + tq * 2;
                *(float2*)&qp[row * DD + col] = make_float2(acc[mi][ni][0], acc[mi][ni][1]);
                *(float2*)&qp[(row + 8) * DD + col] = make_float2(acc[mi][ni][2], acc[mi][ni][3]);
            }

        grid_barrier();  // qp ready everywhere

        // ============ CG phase (warp-per-row) ============
        {
            const float sh = g_shift[crow];
            float4 p[4], q[4];
#pragma unroll
            for (int i = 0; i < 4; i++) {
                int idx = cbase + i * 128;
                p[i] = *(const float4*)&g_p[idx];
                float4 q0 = *(const float4*)&g_qp[0][idx];
                float4 q1 = *(const float4*)&g_qp[1][idx];
                q[i].x = q0.x + q1.x + sh * p[i].x;
                q[i].y = q0.y + q1.y + sh * p[i].y;
                q[i].z = q0.z + q1.z + sh * p[i].z;
                q[i].w = q0.w + q1.w + sh * p[i].w;
            }
            float dot = 0.0f;
#pragma unroll
            for (int i = 0; i < 4; i++)
                dot += p[i].x * q[i].x + p[i].y * q[i].y + p[i].z * q[i].z + p[i].w * q[i].w;
            dot = warp_sum(dot);
            float rro = g_rr[crow];
            float alpha = rro / fmaxf(dot, 1e-30f);

            if (it == NITER - 1) {
                float os = g_oscale[crow];
#pragma unroll
                for (int i = 0; i < 4; i++) {
                    int idx = cbase + i * 128;
                    float4 y = *(const float4*)&g_y[idx];
                    float4 o;
                    o.x = os * (y.x + alpha * p[i].x);
                    o.y = os * (y.y + alpha * p[i].y);
                    o.z = os * (y.z + alpha * p[i].z);
                    o.w = os * (y.w + alpha * p[i].w);
                    *(float4*)&out[idx] = o;
                }
            } else {
                float rr_new = 0.0f;
                float4 r[4];
#pragma unroll
                for (int i = 0; i < 4; i++) {
                    int idx = cbase + i * 128;
                    float4 y = *(const float4*)&g_y[idx];
                    y.x += alpha * p[i].x; y.y += alpha * p[i].y;
                    y.z += alpha * p[i].z; y.w += alpha * p[i].w;
                    *(float4*)&g_y[idx] = y;
                    r[i] = *(const float4*)&g_r[idx];
                    r[i].x -= alpha * q[i].x; r[i].y -= alpha * q[i].y;
                    r[i].z -= alpha * q[i].z; r[i].w -= alpha * q[i].w;
                    *(float4*)&g_r[idx] = r[i];
                    rr_new += r[i].x * r[i].x + r[i].y * r[i].y +
                              r[i].z * r[i].z + r[i].w * r[i].w;
                }
                rr_new = warp_sum(rr_new);
                float beta = rr_new / fmaxf(rro, 1e-30f);
                if (lid == 0) g_rr[crow] = rr_new;

#pragma unroll
                for (int i = 0; i < 4; i++) {
                    int idx = cbase + i * 128;
                    float4 pn;
                    pn.x = r[i].x + beta * p[i].x;
                    pn.y = r[i].y + beta * p[i].y;
                    pn.z = r[i].z + beta * p[i].z;
                    pn.w = r[i].w + beta * p[i].w;
                    *(float4*)&g_p[idx] = pn;
                    __nv_bfloat162 h01, h23, l01, l23;
                    h01.x = __float2bfloat16(pn.x);
                    h01.y = __float2bfloat16(pn.y);
                    h23.x = __float2bfloat16(pn.z);
                    h23.y = __float2bfloat16(pn.w);
                    l01.x = __float2bfloat16(pn.x - __bfloat162float(h01.x));
                    l01.y = __float2bfloat16(pn.y - __bfloat162float(h01.y));
                    l23.x = __float2bfloat16(pn.z - __bfloat162float(h23.x));
                    l23.y = __float2bfloat16(pn.w - __bfloat162float(h23.y));
                    *(__nv_bfloat162*)&g_p_hi[idx] = h01;
                    *(__nv_bfloat162*)&g_p_hi[idx + 2] = h23;
                    *(__nv_bfloat162*)&g_p_lo[idx] = l01;
                    *(__nv_bfloat162*)&g_p_lo[idx + 2] = l23;
                }
            }
        }

        if (it < NITER - 1) grid_barrier();  // p ready for next GEMM
    }
}

// ---------------------------------------------------------------------------
extern "C" void kernel_launch(void* const* d_in, const int* in_sizes, int n_in,
                              void* d_out, int out_size) {
    const float* x = (const float*)d_in[0];
    const float* t = (const float*)d_in[1];
    const float* mu = (const float*)d_in[2];
    const float* cov = (const float*)d_in[3];
    float* out = (float*)d_out;

    init_kernel<<<BATCH, 256>>>(x, t, mu);
    prep_c_kernel<<<DD, 256>>>(cov);
    cg_persistent_kernel<<<NCTA, 128>>>(out);
}

// round 10
// speedup vs baseline: 1.3114x; 1.3114x over previous
#include <cuda_runtime.h>
#include <cuda_bf16.h>
#include <cstdint>

// Problem constants
#define BATCH 512
#define DD 512
#define NITER 6
#define SPLITK 2
#define KPER (DD / SPLITK)      // 256 per CTA
#define BK 64                   // k-chunk staged in smem
#define APITCH 72               // padded smem pitch (bank-conflict-free ldmatrix)

// ---------------------------------------------------------------------------
// Scratch (device globals — no allocation allowed)
// ---------------------------------------------------------------------------
__device__ float g_r[BATCH * DD];
__device__ float g_p[BATCH * DD];
__device__ float g_y[BATCH * DD];
__device__ float g_qp[SPLITK][BATCH * DD];
__device__ __nv_bfloat16 g_p_hi[BATCH * DD];
__device__ __nv_bfloat16 g_p_lo[BATCH * DD];
__device__ __nv_bfloat16 g_c_hi[DD * DD];
__device__ __nv_bfloat16 g_c_lo[DD * DD];
__device__ float g_shift[BATCH];
__device__ float g_oscale[BATCH];
__device__ float g_rr[BATCH];

// ---------------------------------------------------------------------------
// PTX helpers (sm_80-era instructions only — safe for plain sm_103 ptxas)
// ---------------------------------------------------------------------------
__device__ __forceinline__ uint32_t smem_u32(const void* p) {
    uint32_t a;
    asm("{ .reg .u64 t; cvta.to.shared.u64 t, %1; cvt.u32.u64 %0, t; }"
        : "=r"(a) : "l"(p));
    return a;
}

__device__ __forceinline__ void ldsm4(uint32_t* r, uint32_t addr) {
    asm volatile("ldmatrix.sync.aligned.m8n8.x4.shared.b16 {%0,%1,%2,%3}, [%4];"
                 : "=r"(r[0]), "=r"(r[1]), "=r"(r[2]), "=r"(r[3]) : "r"(addr));
}

__device__ __forceinline__ void mma_bf16(float* d, const uint32_t* a,
                                         uint32_t b0, uint32_t b1) {
    asm volatile(
        "mma.sync.aligned.m16n8k16.row.col.f32.bf16.bf16.f32 "
        "{%0,%1,%2,%3}, {%4,%5,%6,%7}, {%8,%9}, {%0,%1,%2,%3};"
        : "+f"(d[0]), "+f"(d[1]), "+f"(d[2]), "+f"(d[3])
        : "r"(a[0]), "r"(a[1]), "r"(a[2]), "r"(a[3]), "r"(b0), "r"(b1));
}

__device__ __forceinline__ float warp_sum(float v) {
#pragma unroll
    for (int m = 16; m > 0; m >>= 1)
        v += __shfl_xor_sync(0xFFFFFFFFu, v, m);
    return v;
}

// ---------------------------------------------------------------------------
// Init (warp-per-row, zero barriers): per-row scalars, rhs = exp(.5B)x - mu,
// r = p = rhs, y = 0, rr = ||rhs||^2, p hi/lo split.
// Grid: BATCH/8 = 64 blocks x 256 thr (8 warps; warp <-> row).
// ---------------------------------------------------------------------------
__global__ __launch_bounds__(256) void init_kernel(const float* __restrict__ x,
                                                   const float* __restrict__ t,
                                                   const float* __restrict__ mu) {
    const int lane = threadIdx.x & 31;
    const int b = blockIdx.x * 8 + (threadIdx.x >> 5);
    float tv = t[b];
    float B = 9.95f * tv * tv + 0.1f * tv;
    float eh = expf(0.5f * B);
    if (lane == 0) {
        g_shift[b] = expm1f(B);
        g_oscale[b] = -(eh * sqrtf(-expm1f(-B)));
    }
    const int base = b * DD + lane * 4;
    float acc = 0.0f;
#pragma unroll
    for (int i = 0; i < 4; i++) {
        int idx = base + i * 128;
        float4 xv = *(const float4*)&x[idx];
        float4 mv = *(const float4*)&mu[lane * 4 + i * 128];
        float4 v;
        v.x = eh * xv.x - mv.x;
        v.y = eh * xv.y - mv.y;
        v.z = eh * xv.z - mv.z;
        v.w = eh * xv.w - mv.w;
        *(float4*)&g_r[idx] = v;
        *(float4*)&g_p[idx] = v;
        *(float4*)&g_y[idx] = make_float4(0.f, 0.f, 0.f, 0.f);
        __nv_bfloat162 h01, h23, l01, l23;
        h01.x = __float2bfloat16(v.x); h01.y = __float2bfloat16(v.y);
        h23.x = __float2bfloat16(v.z); h23.y = __float2bfloat16(v.w);
        l01.x = __float2bfloat16(v.x - __bfloat162float(h01.x));
        l01.y = __float2bfloat16(v.y - __bfloat162float(h01.y));
        l23.x = __float2bfloat16(v.z - __bfloat162float(h23.x));
        l23.y = __float2bfloat16(v.w - __bfloat162float(h23.y));
        *(__nv_bfloat162*)&g_p_hi[idx] = h01;
        *(__nv_bfloat162*)&g_p_hi[idx + 2] = h23;
        *(__nv_bfloat162*)&g_p_lo[idx] = l01;
        *(__nv_bfloat162*)&g_p_lo[idx + 2] = l23;
        acc += v.x * v.x + v.y * v.y + v.z * v.z + v.w * v.w;
    }
    acc = warp_sum(acc);
    if (lane == 0) g_rr[b] = acc;
}

// ---------------------------------------------------------------------------
// Prep C: bf16 hi/lo split of posterior_cov (symmetric: row n == col n)
// ---------------------------------------------------------------------------
__global__ __launch_bounds__(256) void prep_c_kernel(const float* __restrict__ cov) {
    int i = blockIdx.x;
    int tid = threadIdx.x;
#pragma unroll
    for (int k = 0; k < 2; k++) {
        int idx = i * DD + tid + k * 256;
        float v = cov[idx];
        __nv_bfloat16 h = __float2bfloat16(v);
        g_c_hi[idx] = h;
        g_c_lo[idx] = __float2bfloat16(v - __bfloat162float(h));
    }
}

// ---------------------------------------------------------------------------
// mma.sync GEMM: qp[kz][m][n] = sum_{k in slice} p[m][k] * C[n][k]
// (R7 form, validated fastest: precomputed bf16 hi/lo operands)
// ---------------------------------------------------------------------------
__global__ __launch_bounds__(128) void gemm_mma_kernel() {
    __shared__ __nv_bfloat16 sAhi[64][APITCH];
    __shared__ __nv_bfloat16 sAlo[64][APITCH];
    __shared__ __nv_bfloat16 sBhi[64][APITCH];
    __shared__ __nv_bfloat16 sBlo[64][APITCH];

    const int tid = threadIdx.x;
    const int lid = tid & 31;
    const int wid = tid >> 5;
    const int wm = (wid & 1) * 32;
    const int wn = (wid >> 1) * 32;
    const int bm = blockIdx.y * 64;
    const int bn = blockIdx.x * 64;
    const int kbase = blockIdx.z * KPER;

    float acc[2][4][4];
#pragma unroll
    for (int i = 0; i < 2; i++)
#pragma unroll
        for (int j = 0; j < 4; j++)
#pragma unroll
            for (int v = 0; v < 4; v++) acc[i][j][v] = 0.0f;

    const int lrow = lid & 15;
    const int lcol8 = (lid >> 4) * 8;

    for (int kc = kbase; kc < kbase + KPER; kc += BK) {
        __syncthreads();
#pragma unroll
        for (int i = 0; i < 4; i++) {
            int slot = tid + 128 * i;
            int row = slot >> 3;
            int c8 = (slot & 7) * 8;
            *(uint4*)&sAhi[row][c8] = *(const uint4*)&g_p_hi[(bm + row) * DD + kc + c8];
            *(uint4*)&sAlo[row][c8] = *(const uint4*)&g_p_lo[(bm + row) * DD + kc + c8];
            *(uint4*)&sBhi[row][c8] = *(const uint4*)&g_c_hi[(bn + row) * DD + kc + c8];
            *(uint4*)&sBlo[row][c8] = *(const uint4*)&g_c_lo[(bn + row) * DD + kc + c8];
        }
        __syncthreads();

#pragma unroll
        for (int ks = 0; ks < BK / 16; ks++) {
            int kk = ks * 16 + lcol8;
            uint32_t ahi[2][4], alo[2][4], bhi[2][4], blo[2][4];
#pragma unroll
            for (int mi = 0; mi < 2; mi++) {
                ldsm4(ahi[mi], smem_u32(&sAhi[wm + mi * 16 + lrow][kk]));
                ldsm4(alo[mi], smem_u32(&sAlo[wm + mi * 16 + lrow][kk]));
            }
#pragma unroll
            for (int nh = 0; nh < 2; nh++) {
                ldsm4(bhi[nh], smem_u32(&sBhi[wn + nh * 16 + lrow][kk]));
                ldsm4(blo[nh], smem_u32(&sBlo[wn + nh * 16 + lrow][kk]));
            }
#pragma unroll
            for (int mi = 0; mi < 2; mi++)
#pragma unroll
                for (int ni = 0; ni < 4; ni++) {
                    int nh = ni >> 1, sb = ni & 1;
                    mma_bf16(acc[mi][ni], ahi[mi], bhi[nh][sb], bhi[nh][sb + 2]);
                    mma_bf16(acc[mi][ni], ahi[mi], blo[nh][sb], blo[nh][sb + 2]);
                    mma_bf16(acc[mi][ni], alo[mi], bhi[nh][sb], bhi[nh][sb + 2]);
                }
        }
    }

    float* qp = g_qp[blockIdx.z];
    const int g = lid >> 2, tq = lid & 3;
#pragma unroll
    for (int mi = 0; mi < 2; mi++)
#pragma unroll
        for (int ni = 0; ni < 4; ni++) {
            int row = bm + wm + mi * 16 + g;
            int col = bn + wn + ni * 8 + tq * 2;
            *(float2*)&qp[row * DD + col] = make_float2(acc[mi][ni][0], acc[mi][ni][1]);
            *(float2*)&qp[(row + 8) * DD + col] = make_float2(acc[mi][ni][2], acc[mi][ni][3]);
        }
}

// ---------------------------------------------------------------------------
// CG update: 2 warps per row, 64 threads/row, 8 elems (2 float4) per thread.
// (R8 form, validated 6.69us) + p hi/lo stores for the GEMM.
// LAST=true: out = oscale*(y + alpha*p), skip the rest.
// ---------------------------------------------------------------------------
template <bool LAST>
__global__ __launch_bounds__(256) void cg_update_kernel(float* __restrict__ out) {
    const int tid = threadIdx.x;
    const int rl = tid >> 6;           // row within block (0..3)
    const int sub = tid & 63;          // thread within row
    const int w = (tid >> 5) & 1;      // warp within row
    const int b = blockIdx.x * 4 + rl;
    const float sh = g_shift[b];
    const int base = b * DD + sub * 8;

    __shared__ float sdot[4][2];
    __shared__ float srr[4][2];

    float4 p[2], q[2], r[2];
#pragma unroll
    for (int i = 0; i < 2; i++) {
        int idx = base + i * 4;
        p[i] = *(const float4*)&g_p[idx];
        float4 q0 = *(const float4*)&g_qp[0][idx];
        float4 q1 = *(const float4*)&g_qp[1][idx];
        q[i].x = q0.x + q1.x + sh * p[i].x;
        q[i].y = q0.y + q1.y + sh * p[i].y;
        q[i].z = q0.z + q1.z + sh * p[i].z;
        q[i].w = q0.w + q1.w + sh * p[i].w;
        if (!LAST) r[i] = *(const float4*)&g_r[idx];
    }

    float dot = 0.0f;
#pragma unroll
    for (int i = 0; i < 2; i++)
        dot += p[i].x * q[i].x + p[i].y * q[i].y + p[i].z * q[i].z + p[i].w * q[i].w;
    dot = warp_sum(dot);
    if ((tid & 31) == 0) sdot[rl][w] = dot;
    __syncthreads();
    float rro = g_rr[b];
    float alpha = rro / fmaxf(sdot[rl][0] + sdot[rl][1], 1e-30f);

    if (LAST) {
        float os = g_oscale[b];
#pragma unroll
        for (int i = 0; i < 2; i++) {
            int idx = base + i * 4;
            float4 y = *(const float4*)&g_y[idx];
            float4 o;
            o.x = os * (y.x + alpha * p[i].x);
            o.y = os * (y.y + alpha * p[i].y);
            o.z = os * (y.z + alpha * p[i].z);
            o.w = os * (y.w + alpha * p[i].w);
            *(float4*)&out[idx] = o;
        }
        return;
    }

    float rr_new = 0.0f;
#pragma unroll
    for (int i = 0; i < 2; i++) {
        int idx = base + i * 4;
        float4 y = *(const float4*)&g_y[idx];
        y.x += alpha * p[i].x; y.y += alpha * p[i].y;
        y.z += alpha * p[i].z; y.w += alpha * p[i].w;
        *(float4*)&g_y[idx] = y;
        r[i].x -= alpha * q[i].x; r[i].y -= alpha * q[i].y;
        r[i].z -= alpha * q[i].z; r[i].w -= alpha * q[i].w;
        *(float4*)&g_r[idx] = r[i];
        rr_new += r[i].x * r[i].x + r[i].y * r[i].y +
                  r[i].z * r[i].z + r[i].w * r[i].w;
    }
    rr_new = warp_sum(rr_new);
    if ((tid & 31) == 0) srr[rl][w] = rr_new;
    __syncthreads();
    rr_new = srr[rl][0] + srr[rl][1];
    float beta = rr_new / fmaxf(rro, 1e-30f);
    if (sub == 0) g_rr[b] = rr_new;

#pragma unroll
    for (int i = 0; i < 2; i++) {
        int idx = base + i * 4;
        float4 pn;
        pn.x = r[i].x + beta * p[i].x;
        pn.y = r[i].y + beta * p[i].y;
        pn.z = r[i].z + beta * p[i].z;
        pn.w = r[i].w + beta * p[i].w;
        *(float4*)&g_p[idx] = pn;
        __nv_bfloat162 h01, h23, l01, l23;
        h01.x = __float2bfloat16(pn.x);
        h01.y = __float2bfloat16(pn.y);
        h23.x = __float2bfloat16(pn.z);
        h23.y = __float2bfloat16(pn.w);
        l01.x = __float2bfloat16(pn.x - __bfloat162float(h01.x));
        l01.y = __float2bfloat16(pn.y - __bfloat162float(h01.y));
        l23.x = __float2bfloat16(pn.z - __bfloat162float(h23.x));
        l23.y = __float2bfloat16(pn.w - __bfloat162float(h23.y));
        *(__nv_bfloat162*)&g_p_hi[idx] = h01;
        *(__nv_bfloat162*)&g_p_hi[idx + 2] = h23;
        *(__nv_bfloat162*)&g_p_lo[idx] = l01;
        *(__nv_bfloat162*)&g_p_lo[idx + 2] = l23;
    }
}

// ---------------------------------------------------------------------------
extern "C" void kernel_launch(void* const* d_in, const int* in_sizes, int n_in,
                              void* d_out, int out_size) {
    const float* x = (const float*)d_in[0];
    const float* t = (const float*)d_in[1];
    const float* mu = (const float*)d_in[2];
    const float* cov = (const float*)d_in[3];
    float* out = (float*)d_out;

    init_kernel<<<BATCH / 8, 256>>>(x, t, mu);
    prep_c_kernel<<<DD, 256>>>(cov);
    dim3 ggrid(DD / 64, BATCH / 64, SPLITK);  // (8, 8, 2) = 128 CTAs
    for (int it = 0; it < NITER - 1; it++) {
        gemm_mma_kernel<<<ggrid, 128>>>();
        cg_update_kernel<false><<<BATCH / 4, 256>>>(nullptr);
    }
    gemm_mma_kernel<<<ggrid, 128>>>();
    cg_update_kernel<true><<<BATCH / 4, 256>>>(out);
}

// round 11
// speedup vs baseline: 1.4180x; 1.0813x over previous
#include <cuda_runtime.h>
#include <cuda_bf16.h>
#include <cstdint>

// Problem constants
#define BATCH 512
#define DD 512
#define NITER 6
#define SPLITK 2
#define KPER (DD / SPLITK)      // 256 per CTA
#define BK 64                   // k-chunk staged in smem
#define APITCH 72               // padded smem pitch (bank-conflict-free ldmatrix)

// ---------------------------------------------------------------------------
// Scratch (device globals — no allocation allowed)
// ---------------------------------------------------------------------------
__device__ float g_r[BATCH * DD];
__device__ float g_p[BATCH * DD];
__device__ float g_y[BATCH * DD];
__device__ float g_qp[SPLITK][BATCH * DD];
__device__ __nv_bfloat16 g_p_hi[BATCH * DD];
__device__ __nv_bfloat16 g_p_lo[BATCH * DD];
__device__ __nv_bfloat16 g_c_hi[DD * DD];
__device__ __nv_bfloat16 g_c_lo[DD * DD];
__device__ float g_shift[BATCH];
__device__ float g_oscale[BATCH];
__device__ float g_rr[BATCH];

// ---------------------------------------------------------------------------
// PTX helpers (sm_80-era instructions only — safe for plain sm_103 ptxas)
// ---------------------------------------------------------------------------
__device__ __forceinline__ uint32_t smem_u32(const void* p) {
    uint32_t a;
    asm("{ .reg .u64 t; cvta.to.shared.u64 t, %1; cvt.u32.u64 %0, t; }"
        : "=r"(a) : "l"(p));
    return a;
}

__device__ __forceinline__ void ldsm4(uint32_t* r, uint32_t addr) {
    asm volatile("ldmatrix.sync.aligned.m8n8.x4.shared.b16 {%0,%1,%2,%3}, [%4];"
                 : "=r"(r[0]), "=r"(r[1]), "=r"(r[2]), "=r"(r[3]) : "r"(addr));
}

__device__ __forceinline__ void mma_bf16(float* d, const uint32_t* a,
                                         uint32_t b0, uint32_t b1) {
    asm volatile(
        "mma.sync.aligned.m16n8k16.row.col.f32.bf16.bf16.f32 "
        "{%0,%1,%2,%3}, {%4,%5,%6,%7}, {%8,%9}, {%0,%1,%2,%3};"
        : "+f"(d[0]), "+f"(d[1]), "+f"(d[2]), "+f"(d[3])
        : "r"(a[0]), "r"(a[1]), "r"(a[2]), "r"(a[3]), "r"(b0), "r"(b1));
}

__device__ __forceinline__ float warp_sum(float v) {
#pragma unroll
    for (int m = 16; m > 0; m >>= 1)
        v += __shfl_xor_sync(0xFFFFFFFFu, v, m);
    return v;
}

// ---------------------------------------------------------------------------
// Init (warp-per-row, zero barriers)
// ---------------------------------------------------------------------------
__global__ __launch_bounds__(256) void init_kernel(const float* __restrict__ x,
                                                   const float* __restrict__ t,
                                                   const float* __restrict__ mu) {
    const int lane = threadIdx.x & 31;
    const int b = blockIdx.x * 8 + (threadIdx.x >> 5);
    float tv = t[b];
    float B = 9.95f * tv * tv + 0.1f * tv;
    float eh = expf(0.5f * B);
    if (lane == 0) {
        g_shift[b] = expm1f(B);
        g_oscale[b] = -(eh * sqrtf(-expm1f(-B)));
    }
    const int base = b * DD + lane * 4;
    float acc = 0.0f;
#pragma unroll
    for (int i = 0; i < 4; i++) {
        int idx = base + i * 128;
        float4 xv = *(const float4*)&x[idx];
        float4 mv = *(const float4*)&mu[lane * 4 + i * 128];
        float4 v;
        v.x = eh * xv.x - mv.x;
        v.y = eh * xv.y - mv.y;
        v.z = eh * xv.z - mv.z;
        v.w = eh * xv.w - mv.w;
        *(float4*)&g_r[idx] = v;
        *(float4*)&g_p[idx] = v;
        *(float4*)&g_y[idx] = make_float4(0.f, 0.f, 0.f, 0.f);
        __nv_bfloat162 h01, h23, l01, l23;
        h01.x = __float2bfloat16(v.x); h01.y = __float2bfloat16(v.y);
        h23.x = __float2bfloat16(v.z); h23.y = __float2bfloat16(v.w);
        l01.x = __float2bfloat16(v.x - __bfloat162float(h01.x));
        l01.y = __float2bfloat16(v.y - __bfloat162float(h01.y));
        l23.x = __float2bfloat16(v.z - __bfloat162float(h23.x));
        l23.y = __float2bfloat16(v.w - __bfloat162float(h23.y));
        *(__nv_bfloat162*)&g_p_hi[idx] = h01;
        *(__nv_bfloat162*)&g_p_hi[idx + 2] = h23;
        *(__nv_bfloat162*)&g_p_lo[idx] = l01;
        *(__nv_bfloat162*)&g_p_lo[idx + 2] = l23;
        acc += v.x * v.x + v.y * v.y + v.z * v.z + v.w * v.w;
    }
    acc = warp_sum(acc);
    if (lane == 0) g_rr[b] = acc;
}

// ---------------------------------------------------------------------------
// Prep C: bf16 hi/lo split of posterior_cov (symmetric: row n == col n)
// ---------------------------------------------------------------------------
__global__ __launch_bounds__(256) void prep_c_kernel(const float* __restrict__ cov) {
    int i = blockIdx.x;
    int tid = threadIdx.x;
#pragma unroll
    for (int k = 0; k < 2; k++) {
        int idx = i * DD + tid + k * 256;
        float v = cov[idx];
        __nv_bfloat16 h = __float2bfloat16(v);
        g_c_hi[idx] = h;
        g_c_lo[idx] = __float2bfloat16(v - __bfloat162float(h));
    }
}

// ---------------------------------------------------------------------------
// mma.sync GEMM (R7 form, validated fastest — unchanged)
// ---------------------------------------------------------------------------
__global__ __launch_bounds__(128) void gemm_mma_kernel() {
    __shared__ __nv_bfloat16 sAhi[64][APITCH];
    __shared__ __nv_bfloat16 sAlo[64][APITCH];
    __shared__ __nv_bfloat16 sBhi[64][APITCH];
    __shared__ __nv_bfloat16 sBlo[64][APITCH];

    const int tid = threadIdx.x;
    const int lid = tid & 31;
    const int wid = tid >> 5;
    const int wm = (wid & 1) * 32;
    const int wn = (wid >> 1) * 32;
    const int bm = blockIdx.y * 64;
    const int bn = blockIdx.x * 64;
    const int kbase = blockIdx.z * KPER;

    float acc[2][4][4];
#pragma unroll
    for (int i = 0; i < 2; i++)
#pragma unroll
        for (int j = 0; j < 4; j++)
#pragma unroll
            for (int v = 0; v < 4; v++) acc[i][j][v] = 0.0f;

    const int lrow = lid & 15;
    const int lcol8 = (lid >> 4) * 8;

    for (int kc = kbase; kc < kbase + KPER; kc += BK) {
        __syncthreads();
#pragma unroll
        for (int i = 0; i < 4; i++) {
            int slot = tid + 128 * i;
            int row = slot >> 3;
            int c8 = (slot & 7) * 8;
            *(uint4*)&sAhi[row][c8] = *(const uint4*)&g_p_hi[(bm + row) * DD + kc + c8];
            *(uint4*)&sAlo[row][c8] = *(const uint4*)&g_p_lo[(bm + row) * DD + kc + c8];
            *(uint4*)&sBhi[row][c8] = *(const uint4*)&g_c_hi[(bn + row) * DD + kc + c8];
            *(uint4*)&sBlo[row][c8] = *(const uint4*)&g_c_lo[(bn + row) * DD + kc + c8];
        }
        __syncthreads();

#pragma unroll
        for (int ks = 0; ks < BK / 16; ks++) {
            int kk = ks * 16 + lcol8;
            uint32_t ahi[2][4], alo[2][4], bhi[2][4], blo[2][4];
#pragma unroll
            for (int mi = 0; mi < 2; mi++) {
                ldsm4(ahi[mi], smem_u32(&sAhi[wm + mi * 16 + lrow][kk]));
                ldsm4(alo[mi], smem_u32(&sAlo[wm + mi * 16 + lrow][kk]));
            }
#pragma unroll
            for (int nh = 0; nh < 2; nh++) {
                ldsm4(bhi[nh], smem_u32(&sBhi[wn + nh * 16 + lrow][kk]));
                ldsm4(blo[nh], smem_u32(&sBlo[wn + nh * 16 + lrow][kk]));
            }
#pragma unroll
            for (int mi = 0; mi < 2; mi++)
#pragma unroll
                for (int ni = 0; ni < 4; ni++) {
                    int nh = ni >> 1, sb = ni & 1;
                    mma_bf16(acc[mi][ni], ahi[mi], bhi[nh][sb], bhi[nh][sb + 2]);
                    mma_bf16(acc[mi][ni], ahi[mi], blo[nh][sb], blo[nh][sb + 2]);
                    mma_bf16(acc[mi][ni], alo[mi], bhi[nh][sb], bhi[nh][sb + 2]);
                }
        }
    }

    float* qp = g_qp[blockIdx.z];
    const int g = lid >> 2, tq = lid & 3;
#pragma unroll
    for (int mi = 0; mi < 2; mi++)
#pragma unroll
        for (int ni = 0; ni < 4; ni++) {
            int row = bm + wm + mi * 16 + g;
            int col = bn + wn + ni * 8 + tq * 2;
            *(float2*)&qp[row * DD + col] = make_float2(acc[mi][ni][0], acc[mi][ni][1]);
            *(float2*)&qp[(row + 8) * DD + col] = make_float2(acc[mi][ni][2], acc[mi][ni][3]);
        }
}

// ---------------------------------------------------------------------------
// CG update: 4 warps per row, 128 threads/row, 4 elems (1 float4) per thread.
// 2 rows per 256-thread block -> 256 blocks. r,y loads hoisted above the
// dot reduction so they overlap the shfl tree.
// LAST=true: out = oscale*(y + alpha*p), skip the rest.
// ---------------------------------------------------------------------------
template <bool LAST>
__global__ __launch_bounds__(256) void cg_update_kernel(float* __restrict__ out) {
    const int tid = threadIdx.x;
    const int rl = tid >> 7;           // row within block (0..1)
    const int sub = tid & 127;         // thread within row
    const int w = (tid >> 5) & 3;      // warp within row (0..3)
    const int b = blockIdx.x * 2 + rl;
    const float sh = g_shift[b];
    const int idx = b * DD + sub * 4;

    __shared__ float sdot[2][4];
    __shared__ float srr[2][4];

    float4 p = *(const float4*)&g_p[idx];
    float4 q0 = *(const float4*)&g_qp[0][idx];
    float4 q1 = *(const float4*)&g_qp[1][idx];
    float4 q;
    q.x = q0.x + q1.x + sh * p.x;
    q.y = q0.y + q1.y + sh * p.y;
    q.z = q0.z + q1.z + sh * p.z;
    q.w = q0.w + q1.w + sh * p.w;
    // Hoisted loads — independent of alpha, overlap the reduction
    float4 y = *(const float4*)&g_y[idx];
    float4 r;
    if (!LAST) r = *(const float4*)&g_r[idx];

    float dot = p.x * q.x + p.y * q.y + p.z * q.z + p.w * q.w;
    dot = warp_sum(dot);
    if ((tid & 31) == 0) sdot[rl][w] = dot;
    __syncthreads();
    float rro = g_rr[b];
    float alpha = rro / fmaxf((sdot[rl][0] + sdot[rl][1]) +
                              (sdot[rl][2] + sdot[rl][3]), 1e-30f);

    if (LAST) {
        float os = g_oscale[b];
        float4 o;
        o.x = os * (y.x + alpha * p.x);
        o.y = os * (y.y + alpha * p.y);
        o.z = os * (y.z + alpha * p.z);
        o.w = os * (y.w + alpha * p.w);
        *(float4*)&out[idx] = o;
        return;
    }

    y.x += alpha * p.x; y.y += alpha * p.y;
    y.z += alpha * p.z; y.w += alpha * p.w;
    *(float4*)&g_y[idx] = y;
    r.x -= alpha * q.x; r.y -= alpha * q.y;
    r.z -= alpha * q.z; r.w -= alpha * q.w;
    *(float4*)&g_r[idx] = r;
    float rr_new = r.x * r.x + r.y * r.y + r.z * r.z + r.w * r.w;
    rr_new = warp_sum(rr_new);
    if ((tid & 31) == 0) srr[rl][w] = rr_new;
    __syncthreads();
    rr_new = (srr[rl][0] + srr[rl][1]) + (srr[rl][2] + srr[rl][3]);
    float beta = rr_new / fmaxf(rro, 1e-30f);
    if (sub == 0) g_rr[b] = rr_new;

    float4 pn;
    pn.x = r.x + beta * p.x;
    pn.y = r.y + beta * p.y;
    pn.z = r.z + beta * p.z;
    pn.w = r.w + beta * p.w;
    *(float4*)&g_p[idx] = pn;
    __nv_bfloat162 h01, h23, l01, l23;
    h01.x = __float2bfloat16(pn.x);
    h01.y = __float2bfloat16(pn.y);
    h23.x = __float2bfloat16(pn.z);
    h23.y = __float2bfloat16(pn.w);
    l01.x = __float2bfloat16(pn.x - __bfloat162float(h01.x));
    l01.y = __float2bfloat16(pn.y - __bfloat162float(h01.y));
    l23.x = __float2bfloat16(pn.z - __bfloat162float(h23.x));
    l23.y = __float2bfloat16(pn.w - __bfloat162float(h23.y));
    *(__nv_bfloat162*)&g_p_hi[idx] = h01;
    *(__nv_bfloat162*)&g_p_hi[idx + 2] = h23;
    *(__nv_bfloat162*)&g_p_lo[idx] = l01;
    *(__nv_bfloat162*)&g_p_lo[idx + 2] = l23;
}

// ---------------------------------------------------------------------------
extern "C" void kernel_launch(void* const* d_in, const int* in_sizes, int n_in,
                              void* d_out, int out_size) {
    const float* x = (const float*)d_in[0];
    const float* t = (const float*)d_in[1];
    const float* mu = (const float*)d_in[2];
    const float* cov = (const float*)d_in[3];
    float* out = (float*)d_out;

    init_kernel<<<BATCH / 8, 256>>>(x, t, mu);
    prep_c_kernel<<<DD, 256>>>(cov);
    dim3 ggrid(DD / 64, BATCH / 64, SPLITK);  // (8, 8, 2) = 128 CTAs
    for (int it = 0; it < NITER - 1; it++) {
        gemm_mma_kernel<<<ggrid, 128>>>();
        cg_update_kernel<false><<<BATCH / 2, 256>>>(nullptr);
    }
    gemm_mma_kernel<<<ggrid, 128>>>();
    cg_update_kernel<true><<<BATCH / 2, 256>>>(out);
}

// round 14
// speedup vs baseline: 1.7749x; 1.2517x over previous
#include <cuda_runtime.h>
#include <cuda_bf16.h>
#include <cstdint>

// Problem constants
#define BATCH 512
#define DD 512
#define NITER 6
#define SPLITK 4
#define KPER (DD / SPLITK)      // 128 per CTA
#define BK 64                   // k-chunk staged in smem
#define APITCH 72               // padded smem pitch (bank-conflict-free ldmatrix)

// ---------------------------------------------------------------------------
// Scratch (device globals — no allocation allowed)
// ---------------------------------------------------------------------------
__device__ float g_r[BATCH * DD];
__device__ float g_p[BATCH * DD];
__device__ float g_y[BATCH * DD];
__device__ float g_qp[SPLITK][BATCH * DD];
__device__ __nv_bfloat16 g_p_hi[BATCH * DD];
__device__ __nv_bfloat16 g_p_lo[BATCH * DD];
__device__ __nv_bfloat16 g_c_hi[DD * DD];
__device__ __nv_bfloat16 g_c_lo[DD * DD];
__device__ float g_shift[BATCH];
__device__ float g_oscale[BATCH];
__device__ float g_rr[BATCH];

// ---------------------------------------------------------------------------
// PTX helpers (sm_80-era instructions only — safe for plain sm_103 ptxas)
// ---------------------------------------------------------------------------
__device__ __forceinline__ uint32_t smem_u32(const void* p) {
    uint32_t a;
    asm("{ .reg .u64 t; cvta.to.shared.u64 t, %1; cvt.u32.u64 %0, t; }"
        : "=r"(a) : "l"(p));
    return a;
}

__device__ __forceinline__ void ldsm4(uint32_t* r, uint32_t addr) {
    asm volatile("ldmatrix.sync.aligned.m8n8.x4.shared.b16 {%0,%1,%2,%3}, [%4];"
                 : "=r"(r[0]), "=r"(r[1]), "=r"(r[2]), "=r"(r[3]) : "r"(addr));
}

__device__ __forceinline__ void mma_bf16(float* d, const uint32_t* a,
                                         uint32_t b0, uint32_t b1) {
    asm volatile(
        "mma.sync.aligned.m16n8k16.row.col.f32.bf16.bf16.f32 "
        "{%0,%1,%2,%3}, {%4,%5,%6,%7}, {%8,%9}, {%0,%1,%2,%3};"
        : "+f"(d[0]), "+f"(d[1]), "+f"(d[2]), "+f"(d[3])
        : "r"(a[0]), "r"(a[1]), "r"(a[2]), "r"(a[3]), "r"(b0), "r"(b1));
}

__device__ __forceinline__ float warp_sum(float v) {
#pragma unroll
    for (int m = 16; m > 0; m >>= 1)
        v += __shfl_xor_sync(0xFFFFFFFFu, v, m);
    return v;
}

// ---------------------------------------------------------------------------
// Init (warp-per-row, zero barriers)
// ---------------------------------------------------------------------------
__global__ __launch_bounds__(256) void init_kernel(const float* __restrict__ x,
                                                   const float* __restrict__ t,
                                                   const float* __restrict__ mu) {
    const int lane = threadIdx.x & 31;
    const int b = blockIdx.x * 8 + (threadIdx.x >> 5);
    float tv = t[b];
    float B = 9.95f * tv * tv + 0.1f * tv;
    float eh = expf(0.5f * B);
    if (lane == 0) {
        g_shift[b] = expm1f(B);
        g_oscale[b] = -(eh * sqrtf(-expm1f(-B)));
    }
    const int base = b * DD + lane * 4;
    float acc = 0.0f;
#pragma unroll
    for (int i = 0; i < 4; i++) {
        int idx = base + i * 128;
        float4 xv = *(const float4*)&x[idx];
        float4 mv = *(const float4*)&mu[lane * 4 + i * 128];
        float4 v;
        v.x = eh * xv.x - mv.x;
        v.y = eh * xv.y - mv.y;
        v.z = eh * xv.z - mv.z;
        v.w = eh * xv.w - mv.w;
        *(float4*)&g_r[idx] = v;
        *(float4*)&g_p[idx] = v;
        *(float4*)&g_y[idx] = make_float4(0.f, 0.f, 0.f, 0.f);
        __nv_bfloat162 h01, h23, l01, l23;
        h01.x = __float2bfloat16(v.x); h01.y = __float2bfloat16(v.y);
        h23.x = __float2bfloat16(v.z); h23.y = __float2bfloat16(v.w);
        l01.x = __float2bfloat16(v.x - __bfloat162float(h01.x));
        l01.y = __float2bfloat16(v.y - __bfloat162float(h01.y));
        l23.x = __float2bfloat16(v.z - __bfloat162float(h23.x));
        l23.y = __float2bfloat16(v.w - __bfloat162float(h23.y));
        *(__nv_bfloat162*)&g_p_hi[idx] = h01;
        *(__nv_bfloat162*)&g_p_hi[idx + 2] = h23;
        *(__nv_bfloat162*)&g_p_lo[idx] = l01;
        *(__nv_bfloat162*)&g_p_lo[idx + 2] = l23;
        acc += v.x * v.x + v.y * v.y + v.z * v.z + v.w * v.w;
    }
    acc = warp_sum(acc);
    if (lane == 0) g_rr[b] = acc;
}

// ---------------------------------------------------------------------------
// Prep C: bf16 hi/lo split of posterior_cov (symmetric: row n == col n)
// ---------------------------------------------------------------------------
__global__ __launch_bounds__(256) void prep_c_kernel(const float* __restrict__ cov) {
    int i = blockIdx.x;
    int tid = threadIdx.x;
#pragma unroll
    for (int k = 0; k < 2; k++) {
        int idx = i * DD + tid + k * 256;
        float v = cov[idx];
        __nv_bfloat16 h = __float2bfloat16(v);
        g_c_hi[idx] = h;
        g_c_lo[idx] = __float2bfloat16(v - __bfloat162float(h));
    }
}

// ---------------------------------------------------------------------------
// mma.sync GEMM (validated core), split-K = 4: grid (8,8,4) = 256 CTAs
// ---------------------------------------------------------------------------
__global__ __launch_bounds__(128) void gemm_mma_kernel() {
    __shared__ __nv_bfloat16 sAhi[64][APITCH];
    __shared__ __nv_bfloat16 sAlo[64][APITCH];
    __shared__ __nv_bfloat16 sBhi[64][APITCH];
    __shared__ __nv_bfloat16 sBlo[64][APITCH];

    const int tid = threadIdx.x;
    const int lid = tid & 31;
    const int wid = tid >> 5;
    const int wm = (wid & 1) * 32;
    const int wn = (wid >> 1) * 32;
    const int bm = blockIdx.y * 64;
    const int bn = blockIdx.x * 64;
    const int kbase = blockIdx.z * KPER;

    float acc[2][4][4];
#pragma unroll
    for (int i = 0; i < 2; i++)
#pragma unroll
        for (int j = 0; j < 4; j++)
#pragma unroll
            for (int v = 0; v < 4; v++) acc[i][j][v] = 0.0f;

    const int lrow = lid & 15;
    const int lcol8 = (lid >> 4) * 8;

    for (int kc = kbase; kc < kbase + KPER; kc += BK) {
        __syncthreads();
#pragma unroll
        for (int i = 0; i < 4; i++) {
            int slot = tid + 128 * i;
            int row = slot >> 3;
            int c8 = (slot & 7) * 8;
            *(uint4*)&sAhi[row][c8] = *(const uint4*)&g_p_hi[(bm + row) * DD + kc + c8];
            *(uint4*)&sAlo[row][c8] = *(const uint4*)&g_p_lo[(bm + row) * DD + kc + c8];
            *(uint4*)&sBhi[row][c8] = *(const uint4*)&g_c_hi[(bn + row) * DD + kc + c8];
            *(uint4*)&sBlo[row][c8] = *(const uint4*)&g_c_lo[(bn + row) * DD + kc + c8];
        }
        __syncthreads();

#pragma unroll
        for (int ks = 0; ks < BK / 16; ks++) {
            int kk = ks * 16 + lcol8;
            uint32_t ahi[2][4], alo[2][4], bhi[2][4], blo[2][4];
#pragma unroll
            for (int mi = 0; mi < 2; mi++) {
                ldsm4(ahi[mi], smem_u32(&sAhi[wm + mi * 16 + lrow][kk]));
                ldsm4(alo[mi], smem_u32(&sAlo[wm + mi * 16 + lrow][kk]));
            }
#pragma unroll
            for (int nh = 0; nh < 2; nh++) {
                ldsm4(bhi[nh], smem_u32(&sBhi[wn + nh * 16 + lrow][kk]));
                ldsm4(blo[nh], smem_u32(&sBlo[wn + nh * 16 + lrow][kk]));
            }
#pragma unroll
            for (int mi = 0; mi < 2; mi++)
#pragma unroll
                for (int ni = 0; ni < 4; ni++) {
                    int nh = ni >> 1, sb = ni & 1;
                    mma_bf16(acc[mi][ni], ahi[mi], bhi[nh][sb], bhi[nh][sb + 2]);
                    mma_bf16(acc[mi][ni], ahi[mi], blo[nh][sb], blo[nh][sb + 2]);
                    mma_bf16(acc[mi][ni], alo[mi], bhi[nh][sb], bhi[nh][sb + 2]);
                }
        }
    }

    float* qp = g_qp[blockIdx.z];
    const int g = lid >> 2, tq = lid & 3;
#pragma unroll
    for (int mi = 0; mi < 2; mi++)
#pragma unroll
        for (int ni = 0; ni < 4; ni++) {
            int row = bm + wm + mi * 16 + g;
            int col = bn + wn + ni * 8 + tq * 2;
            *(float2*)&qp[row * DD + col] = make_float2(acc[mi][ni][0], acc[mi][ni][1]);
            *(float2*)&qp[(row + 8) * DD + col] = make_float2(acc[mi][ni][2], acc[mi][ni][3]);
        }
}

// ---------------------------------------------------------------------------
// CG update: TWO-phase reduction (rr_new from ACTUAL updated r — the identity
// shortcut is numerically fatal for sh-dominated rows, see R13 post-mortem).
// 1 row per 128-thread block (512 blocks), 4 elems/thread, hoisted loads.
// LAST=true: out = oscale*(y + alpha*p) only.
// ---------------------------------------------------------------------------
template <bool LAST>
__global__ __launch_bounds__(128) void cg_update_kernel(float* __restrict__ out) {
    const int tid = threadIdx.x;
    const int w = tid >> 5;
    const int b = blockIdx.x;
    const float sh = g_shift[b];
    const float rro = g_rr[b];
    const int idx = b * DD + tid * 4;

    __shared__ float sdot[4];
    __shared__ float srr[4];

    float4 p = *(const float4*)&g_p[idx];
    float4 qa = *(const float4*)&g_qp[0][idx];
    float4 qb = *(const float4*)&g_qp[1][idx];
    float4 qc = *(const float4*)&g_qp[2][idx];
    float4 qd = *(const float4*)&g_qp[3][idx];
    float4 q;
    q.x = (qa.x + qb.x) + (qc.x + qd.x) + sh * p.x;
    q.y = (qa.y + qb.y) + (qc.y + qd.y) + sh * p.y;
    q.z = (qa.z + qb.z) + (qc.z + qd.z) + sh * p.z;
    q.w = (qa.w + qb.w) + (qc.w + qd.w) + sh * p.w;
    float4 y = *(const float4*)&g_y[idx];
    float4 r;
    if (!LAST) r = *(const float4*)&g_r[idx];

    float dot = p.x * q.x + p.y * q.y + p.z * q.z + p.w * q.w;
    dot = warp_sum(dot);
    if ((tid & 31) == 0) sdot[w] = dot;
    __syncthreads();
    float alpha = rro / fmaxf((sdot[0] + sdot[1]) + (sdot[2] + sdot[3]), 1e-30f);

    if (LAST) {
        float os = g_oscale[b];
        float4 o;
        o.x = os * (y.x + alpha * p.x);
        o.y = os * (y.y + alpha * p.y);
        o.z = os * (y.z + alpha * p.z);
        o.w = os * (y.w + alpha * p.w);
        *(float4*)&out[idx] = o;
        return;
    }

    y.x += alpha * p.x; y.y += alpha * p.y;
    y.z += alpha * p.z; y.w += alpha * p.w;
    *(float4*)&g_y[idx] = y;
    r.x -= alpha * q.x; r.y -= alpha * q.y;
    r.z -= alpha * q.z; r.w -= alpha * q.w;
    *(float4*)&g_r[idx] = r;

    float rr_new = r.x * r.x + r.y * r.y + r.z * r.z + r.w * r.w;
    rr_new = warp_sum(rr_new);
    if ((tid & 31) == 0) srr[w] = rr_new;
    __syncthreads();
    rr_new = (srr[0] + srr[1]) + (srr[2] + srr[3]);
    float beta = rr_new / fmaxf(rro, 1e-30f);
    if (tid == 0) g_rr[b] = rr_new;

    float4 pn;
    pn.x = r.x + beta * p.x;
    pn.y = r.y + beta * p.y;
    pn.z = r.z + beta * p.z;
    pn.w = r.w + beta * p.w;
    *(float4*)&g_p[idx] = pn;

    __nv_bfloat162 h01, h23, l01, l23;
    h01.x = __float2bfloat16(pn.x);
    h01.y = __float2bfloat16(pn.y);
    h23.x = __float2bfloat16(pn.z);
    h23.y = __float2bfloat16(pn.w);
    l01.x = __float2bfloat16(pn.x - __bfloat162float(h01.x));
    l01.y = __float2bfloat16(pn.y - __bfloat162float(h01.y));
    l23.x = __float2bfloat16(pn.z - __bfloat162float(h23.x));
    l23.y = __float2bfloat16(pn.w - __bfloat162float(h23.y));
    *(__nv_bfloat162*)&g_p_hi[idx] = h01;
    *(__nv_bfloat162*)&g_p_hi[idx + 2] = h23;
    *(__nv_bfloat162*)&g_p_lo[idx] = l01;
    *(__nv_bfloat162*)&g_p_lo[idx + 2] = l23;
}

// ---------------------------------------------------------------------------
extern "C" void kernel_launch(void* const* d_in, const int* in_sizes, int n_in,
                              void* d_out, int out_size) {
    const float* x = (const float*)d_in[0];
    const float* t = (const float*)d_in[1];
    const float* mu = (const float*)d_in[2];
    const float* cov = (const float*)d_in[3];
    float* out = (float*)d_out;

    init_kernel<<<BATCH / 8, 256>>>(x, t, mu);
    prep_c_kernel<<<DD, 256>>>(cov);
    dim3 ggrid(DD / 64, BATCH / 64, SPLITK);  // (8, 8, 4) = 256 CTAs
    for (int it = 0; it < NITER - 1; it++) {
        gemm_mma_kernel<<<ggrid, 128>>>();
        cg_update_kernel<false><<<BATCH, 128>>>(nullptr);
    }
    gemm_mma_kernel<<<ggrid, 128>>>();
    cg_update_kernel<true><<<BATCH, 128>>>(out);
}